// round 1
// baseline (speedup 1.0000x reference)
#include <cuda_runtime.h>
#include <math.h>

#define Bb 64
#define Cc 4
#define Nn 128
#define Kk 64

// One block per (b, row-tile of 32). 256 threads = 8 warps, each warp owns 4 rows.
// Lane owns k = {2*lane, 2*lane+1}. Channels looped inside j so one x load feeds
// 4 channel accumulators. adj row staged channel-interleaved (XOR-swizzled) in smem
// so the inner loop does one broadcast LDS.128 (adj, 4 channels) + one LDS.64 (x) per j.
__global__ __launch_bounds__(256, 4)
void gmp_kernel(const float* __restrict__ x, const float* __restrict__ adj,
                float* __restrict__ out) {
    __shared__ float xs[Nn * Kk];      // 32 KB: x[b]
    __shared__ float ws[8][Nn * 4];    // 16 KB: per-warp adj row, [j][c^swz]

    const int b    = blockIdx.x;
    const int tid  = threadIdx.x;
    const int warp = tid >> 5;
    const int lane = tid & 31;

    // Stage x[b] (128x64 f32) into smem, coalesced float4.
    {
        const float4* xg  = (const float4*)(x + b * (Nn * Kk));
        float4*       xs4 = (float4*)xs;
        #pragma unroll
        for (int t = 0; t < (Nn * Kk / 4) / 256; ++t)
            xs4[tid + 256 * t] = xg[tid + 256 * t];
    }
    __syncthreads();

    const int i_base = blockIdx.y * 32 + warp * 4;
    const int swz    = (lane >> 3) & 3;   // makes the interleaved STS conflict-free

    for (int r = 0; r < 4; ++r) {
        const int i = i_base + r;

        // Stage adj[b, c, i, :] for all 4 channels, channel-interleaved + swizzled.
        // Writes: word index 4*j + (c^swz); the 4 lanes {l, l+8, l+16, l+24} that
        // share 4*j mod 32 get distinct swz -> distinct banks.
        {
            const float* arow = adj + (size_t)((b * Cc) * Nn + i) * Nn;
            #pragma unroll
            for (int c = 0; c < Cc; ++c) {
                const float* ac = arow + c * (Nn * Nn);
                #pragma unroll
                for (int w = 0; w < 4; ++w) {
                    const int j = w * 32 + lane;
                    ws[warp][j * 4 + (c ^ swz)] = ac[j];
                }
            }
        }
        __syncwarp();

        float acc0[Cc], acc1[Cc];
        #pragma unroll
        for (int c = 0; c < Cc; ++c) { acc0[c] = -INFINITY; acc1[c] = -INFINITY; }

        // Inner loop: j unrolled by 32 so the channel un-swizzle is compile-time.
        const float2* xcol = (const float2*)xs + lane;  // xs[j*64 + 2*lane]
        for (int w = 0; w < 4; ++w) {
            #pragma unroll
            for (int u = 0; u < 32; ++u) {
                const int j = w * 32 + u;
                const int s = (u >> 3) & 3;           // == ((j>>3)&3) since w*4 % 4 == 0
                const float4 av = *(const float4*)&ws[warp][j * 4];  // broadcast
                const float2 xv = xcol[j * 32];
                const float a[4] = {av.x, av.y, av.z, av.w};
                #pragma unroll
                for (int c = 0; c < Cc; ++c) {
                    const float acv = a[c ^ s];
                    acc0[c] = fmaxf(acc0[c], acv * xv.x);  // FMUL (fma pipe)
                    acc1[c] = fmaxf(acc1[c], acv * xv.y);  // FMNMX (alu pipe)
                }
            }
        }

        // Match reference channel-sum order (left-assoc).
        const float o0 = ((acc0[0] + acc0[1]) + acc0[2]) + acc0[3];
        const float o1 = ((acc1[0] + acc1[1]) + acc1[2]) + acc1[3];
        float2* op = (float2*)(out + (size_t)(b * Nn + i) * Kk);
        op[lane] = make_float2(o0, o1);
        __syncwarp();   // protect ws reuse next r
    }
}

extern "C" void kernel_launch(void* const* d_in, const int* in_sizes, int n_in,
                              void* d_out, int out_size) {
    // Defensive input-order resolution by element count.
    const float* x;
    const float* adj;
    if (in_sizes[0] == Bb * Nn * Kk) { x = (const float*)d_in[0]; adj = (const float*)d_in[1]; }
    else                             { x = (const float*)d_in[1]; adj = (const float*)d_in[0]; }
    float* out = (float*)d_out;

    dim3 grid(Bb, 4);
    gmp_kernel<<<grid, 256>>>(x, adj, out);
}